// round 1
// baseline (speedup 1.0000x reference)
#include <cuda_runtime.h>
#include <math.h>

#define D_DIM 512
#define MAXQ 4096
#define MAXS 8192

// Scratch (static __device__ arrays; allocation APIs are forbidden)
__device__ float g_qn[(size_t)MAXQ * D_DIM];            // normalized queries   [Q, D]
__device__ float g_kn[(size_t)MAXS * D_DIM];            // normalized keys      [S, D]
__device__ float g_attn[(size_t)MAXQ * MAXS];           // exp kernel           [Q, S]
__device__ float g_vt[(size_t)D_DIM * MAXS];            // gathered proxies^T   [D, S]
__device__ float g_w[(size_t)MAXQ * D_DIM];             // weighted             [Q, D]
__device__ int   g_is64;                                // class index dtype flag

// ---------------------------------------------------------------------------
// Detect whether support_classes is int64 (odd 32-bit words of first 32
// entries all zero) or int32. Values are in [0,1000) so int64 high words are 0.
// For int32 data, P(32 odd-position classes all == 0) ~ (1/1000)^32 ~ 0.
// ---------------------------------------------------------------------------
__global__ void detect_i64_kernel(const int* __restrict__ cls, int S) {
    int is64 = 1;
    int nwords = S < 64 ? S : 64;
    for (int i = 1; i < nwords; i += 2) {
        if (cls[i] != 0) { is64 = 0; break; }
    }
    g_is64 = is64;
}

// ---------------------------------------------------------------------------
// Row-wise L2 normalize: one block (256 threads) per row of 512 floats.
// ---------------------------------------------------------------------------
__global__ void l2norm_kernel(const float* __restrict__ in, float* __restrict__ out) {
    int row = blockIdx.x;
    const float* x = in + (size_t)row * D_DIM;
    float* y = out + (size_t)row * D_DIM;
    int tid = threadIdx.x;

    float v0 = x[tid];
    float v1 = x[tid + 256];
    float s = v0 * v0 + v1 * v1;

    #pragma unroll
    for (int o = 16; o > 0; o >>= 1) s += __shfl_xor_sync(0xffffffffu, s, o);

    __shared__ float ws[8];
    if ((tid & 31) == 0) ws[tid >> 5] = s;
    __syncthreads();
    if (tid < 8) {
        float t = ws[tid];
        #pragma unroll
        for (int o = 4; o > 0; o >>= 1) t += __shfl_xor_sync(0xffu, t, o);
        if (tid == 0) ws[0] = t;
    }
    __syncthreads();

    float nrm = sqrtf(ws[0]);
    float inv = 1.0f / fmaxf(nrm, 1e-12f);
    y[tid] = v0 * inv;
    y[tid + 256] = v1 * inv;
}

// ---------------------------------------------------------------------------
// Gather transposed support proxies: g_vt[d, s] = P[cls[s], d].
// Writes are coalesced over s; reads hit L2 (P is 2 MB, fully resident).
// ---------------------------------------------------------------------------
__global__ void gather_vt_kernel(const int* __restrict__ cls_raw,
                                 const float* __restrict__ P, int S) {
    int s = blockIdx.x * blockDim.x + threadIdx.x;
    int d = blockIdx.y;
    if (s >= S) return;
    int c;
    if (g_is64) c = (int)((const long long*)cls_raw)[s];
    else        c = cls_raw[s];
    g_vt[(size_t)d * S + s] = P[(size_t)c * D_DIM + d];
}

// ---------------------------------------------------------------------------
// NT GEMM: C[M,N] = A[M,K] @ B[N,K]^T, optionally epilogue exp(x - 1).
// 128x128 tile, BK=16, 256 threads, 8x8 per thread. M % 128 == 0, K % 16 == 0,
// N % 8 == 0 assumed; N tail (non-multiple of 128) guarded.
// ---------------------------------------------------------------------------
template <bool EXP_EPI>
__global__ __launch_bounds__(256, 2)
void gemm_nt_kernel(const float* __restrict__ A, const float* __restrict__ B,
                    float* __restrict__ C, int M, int N, int K) {
    __shared__ float As[16][128 + 4];
    __shared__ float Bs[16][128 + 4];

    const int tx = threadIdx.x & 15;   // N direction
    const int ty = threadIdx.x >> 4;   // M direction
    const int m0 = blockIdx.y * 128;
    const int n0 = blockIdx.x * 128;

    const int lrow = threadIdx.x >> 2;        // 0..63
    const int lcol = (threadIdx.x & 3) << 2;  // 0,4,8,12

    float acc[8][8];
    #pragma unroll
    for (int i = 0; i < 8; i++)
        #pragma unroll
        for (int j = 0; j < 8; j++) acc[i][j] = 0.0f;

    for (int k0 = 0; k0 < K; k0 += 16) {
        // Load A tile (transposed into smem)
        #pragma unroll
        for (int r = 0; r < 128; r += 64) {
            float4 v = *(const float4*)(A + (size_t)(m0 + lrow + r) * K + k0 + lcol);
            As[lcol + 0][lrow + r] = v.x;
            As[lcol + 1][lrow + r] = v.y;
            As[lcol + 2][lrow + r] = v.z;
            As[lcol + 3][lrow + r] = v.w;
        }
        // Load B tile (transposed into smem), guard N tail
        #pragma unroll
        for (int r = 0; r < 128; r += 64) {
            int brow = n0 + lrow + r;
            float4 v = make_float4(0.0f, 0.0f, 0.0f, 0.0f);
            if (brow < N)
                v = *(const float4*)(B + (size_t)brow * K + k0 + lcol);
            Bs[lcol + 0][lrow + r] = v.x;
            Bs[lcol + 1][lrow + r] = v.y;
            Bs[lcol + 2][lrow + r] = v.z;
            Bs[lcol + 3][lrow + r] = v.w;
        }
        __syncthreads();

        #pragma unroll
        for (int kk = 0; kk < 16; kk++) {
            float a[8], b[8];
            *(float4*)&a[0] = *(const float4*)&As[kk][ty * 8];
            *(float4*)&a[4] = *(const float4*)&As[kk][ty * 8 + 4];
            *(float4*)&b[0] = *(const float4*)&Bs[kk][tx * 8];
            *(float4*)&b[4] = *(const float4*)&Bs[kk][tx * 8 + 4];
            #pragma unroll
            for (int i = 0; i < 8; i++)
                #pragma unroll
                for (int j = 0; j < 8; j++)
                    acc[i][j] = fmaf(a[i], b[j], acc[i][j]);
        }
        __syncthreads();
    }

    // Epilogue: vectorized stores; N is a multiple of 8 so an 8-wide chunk is
    // either fully in-bounds or fully out.
    #pragma unroll
    for (int i = 0; i < 8; i++) {
        int row = m0 + ty * 8 + i;
        int col = n0 + tx * 8;
        if (col < N) {
            float v[8];
            #pragma unroll
            for (int j = 0; j < 8; j++) {
                float t = acc[i][j];
                if (EXP_EPI) t = __expf(t - 1.0f);
                v[j] = t;
            }
            float* cp = C + (size_t)row * N + col;
            *(float4*)(cp + 0) = *(float4*)&v[0];
            *(float4*)(cp + 4) = *(float4*)&v[4];
        }
    }
}

// ---------------------------------------------------------------------------
// Launch
// ---------------------------------------------------------------------------
extern "C" void kernel_launch(void* const* d_in, const int* in_sizes, int n_in,
                              void* d_out, int out_size) {
    const float* query = (const float*)d_in[0];
    const float* key   = (const float*)d_in[1];
    const float* prox  = (const float*)d_in[2];
    const int*   cls   = (const int*)d_in[3];

    const int Q = in_sizes[0] / D_DIM;   // 4096
    const int S = in_sizes[1] / D_DIM;   // 8192
    const int C = in_sizes[2] / D_DIM;   // 1000
    float* out = (float*)d_out;

    float *qn, *kn, *attn, *vt, *w;
    cudaGetSymbolAddress((void**)&qn,   g_qn);
    cudaGetSymbolAddress((void**)&kn,   g_kn);
    cudaGetSymbolAddress((void**)&attn, g_attn);
    cudaGetSymbolAddress((void**)&vt,   g_vt);
    cudaGetSymbolAddress((void**)&w,    g_w);

    detect_i64_kernel<<<1, 1>>>(cls, S);

    l2norm_kernel<<<Q, 256>>>(query, qn);
    l2norm_kernel<<<S, 256>>>(key, kn);

    {
        dim3 grid((S + 255) / 256, D_DIM);
        gather_vt_kernel<<<grid, 256>>>(cls, prox, S);
    }

    // G1: attn[Q,S] = exp(qn @ kn^T - 1)
    {
        dim3 grid(S / 128, Q / 128);
        gemm_nt_kernel<true><<<grid, 256>>>(qn, kn, attn, Q, S, D_DIM);
    }
    // G2: w[Q,D] = attn @ vt^T   (vt is [D,S], K-major over S)
    {
        dim3 grid(D_DIM / 128, Q / 128);
        gemm_nt_kernel<false><<<grid, 256>>>(attn, vt, w, Q, D_DIM, S);
    }
    // G3: logits[Q,C] = w @ prox^T
    {
        dim3 grid((C + 127) / 128, Q / 128);
        gemm_nt_kernel<false><<<grid, 256>>>(w, prox, out, Q, C, D_DIM);
    }
}

// round 2
// speedup vs baseline: 4.0549x; 4.0549x over previous
#include <cuda_runtime.h>
#include <math.h>
#include <stdint.h>

#define D_DIM 512
#define MAXQ 4096
#define MAXS 8192
#define CPAD 1024
#define NCLS 1000

// Static scratch (no allocation allowed)
__device__ float g_qn[(size_t)MAXQ * D_DIM];       // normalized queries (tf32-rounded)
__device__ float g_kn[(size_t)MAXS * D_DIM];       // normalized keys    (tf32-rounded)
__device__ float g_attn[(size_t)MAXQ * MAXS];      // exp kernel, fp32
__device__ float g_a2[(size_t)MAXQ * CPAD];        // class-bucketed attn sums (tf32-rounded)
__device__ float g_gram[(size_t)NCLS * CPAD];      // P @ P^T (tf32-rounded); pad cols stay 0
__device__ int   g_cls32[MAXS];                    // class ids as int32

// ---------------------------------------------------------------------------
// Helpers
// ---------------------------------------------------------------------------
__device__ __forceinline__ uint32_t f2tf32(float x) {
    uint32_t u;
    asm("cvt.rna.tf32.f32 %0, %1;" : "=r"(u) : "f"(x));
    return u;
}
__device__ __forceinline__ float tf32r(float x) { return __uint_as_float(f2tf32(x)); }

__device__ __forceinline__ void cp16(void* dst_smem, const void* src_gmem) {
    uint32_t d = (uint32_t)__cvta_generic_to_shared(dst_smem);
    asm volatile("cp.async.cg.shared.global [%0], [%1], 16;\n" :: "r"(d), "l"(src_gmem));
}
__device__ __forceinline__ void cp_commit() {
    asm volatile("cp.async.commit_group;\n" ::: "memory");
}
__device__ __forceinline__ void cp_wait1() {
    asm volatile("cp.async.wait_group 1;\n" ::: "memory");
}
__device__ __forceinline__ void cp_wait0() {
    asm volatile("cp.async.wait_group 0;\n" ::: "memory");
}

__device__ __forceinline__ void mma_tf32(float* c, const uint32_t* a, const uint32_t* b) {
    asm volatile(
        "mma.sync.aligned.m16n8k8.row.col.f32.tf32.tf32.f32 "
        "{%0,%1,%2,%3}, {%4,%5,%6,%7}, {%8,%9}, {%0,%1,%2,%3};\n"
        : "+f"(c[0]), "+f"(c[1]), "+f"(c[2]), "+f"(c[3])
        : "r"(a[0]), "r"(a[1]), "r"(a[2]), "r"(a[3]), "r"(b[0]), "r"(b[1]));
}

// ---------------------------------------------------------------------------
// Convert class ids to int32 (auto-detect int64 vs int32 storage)
// ---------------------------------------------------------------------------
__global__ void cls_convert_kernel(const int* __restrict__ raw, int S) {
    __shared__ int is64s;
    if (threadIdx.x == 0) {
        int is64 = 1;
        int nw = S < 64 ? S : 64;
        for (int i = 1; i < nw; i += 2)
            if (raw[i] != 0) { is64 = 0; break; }
        is64s = is64;
    }
    __syncthreads();
    int s = blockIdx.x * blockDim.x + threadIdx.x;
    if (s < S)
        g_cls32[s] = is64s ? (int)((const long long*)raw)[s] : raw[s];
}

// ---------------------------------------------------------------------------
// Row-wise L2 normalize (512 floats/row), output rounded to tf32.
// ---------------------------------------------------------------------------
__global__ void l2norm_kernel(const float* __restrict__ in, float* __restrict__ out) {
    int row = blockIdx.x;
    const float* x = in + (size_t)row * D_DIM;
    float* y = out + (size_t)row * D_DIM;
    int tid = threadIdx.x;

    float v0 = x[tid];
    float v1 = x[tid + 256];
    float s = v0 * v0 + v1 * v1;
    #pragma unroll
    for (int o = 16; o > 0; o >>= 1) s += __shfl_xor_sync(0xffffffffu, s, o);

    __shared__ float ws[8];
    if ((tid & 31) == 0) ws[tid >> 5] = s;
    __syncthreads();
    if (tid < 8) {
        float t = ws[tid];
        #pragma unroll
        for (int o = 4; o > 0; o >>= 1) t += __shfl_xor_sync(0xffu, t, o);
        if (tid == 0) ws[0] = t;
    }
    __syncthreads();

    float inv = 1.0f / fmaxf(sqrtf(ws[0]), 1e-12f);
    y[tid] = tf32r(v0 * inv);
    y[tid + 256] = tf32r(v1 * inv);
}

// ---------------------------------------------------------------------------
// A2[q, c] = sum_{s: cls_s == c} attn[q, s]
// Deterministic: u64 fixed-point (2^46) shared-memory atomics.
// ---------------------------------------------------------------------------
__global__ void a2_kernel(const float* __restrict__ attn, float* __restrict__ A2, int S) {
    __shared__ unsigned long long bins[CPAD];
    int q = blockIdx.x;
    int tid = threadIdx.x;
    for (int c = tid; c < CPAD; c += 256) bins[c] = 0ULL;
    __syncthreads();

    const float* row = attn + (size_t)q * S;
    const float SCALE_UP = 70368744177664.0f;  // 2^46
    for (int s = tid; s < S; s += 256) {
        int c = g_cls32[s];
        unsigned long long fx = (unsigned long long)(row[s] * SCALE_UP);
        atomicAdd(&bins[c], fx);
    }
    __syncthreads();

    const float SCALE_DN = 1.0f / 70368744177664.0f;
    for (int c = tid; c < CPAD; c += 256) {
        float v = (c < NCLS) ? (float)bins[c] * SCALE_DN : 0.0f;
        A2[(size_t)q * CPAD + c] = tf32r(v);
    }
}

// ---------------------------------------------------------------------------
// tf32 NT GEMM: C[M,N] = A[M,K] @ B[N,K]^T
// 128x128 tile, BK=16, 256 threads (8 warps, 32m x 64n each), cp.async
// double-buffered. M/N handled with clamped loads + guarded stores
// (N must be a multiple of 8). K must be a multiple of 16.
// CVT_IN: round operands to tf32 (RN) at fragment load (for raw fp32 inputs).
// EXP_EPI: C = exp(acc - 1).  ROUND_OUT: round stores to tf32.
// ---------------------------------------------------------------------------
template <bool EXP_EPI, bool CVT_IN, bool ROUND_OUT>
__global__ __launch_bounds__(256, 2)
void gemm_tf32_nt(const float* __restrict__ A, const float* __restrict__ B,
                  float* __restrict__ C, int M, int N, int K,
                  int lda, int ldb, int ldc) {
    __shared__ float As[2][128][20];
    __shared__ float Bs[2][128][20];

    const int tid = threadIdx.x;
    const int lane = tid & 31;
    const int wid = tid >> 5;
    const int wm = (wid & 3) * 32;   // warp m-offset in tile
    const int wn = (wid >> 2) * 64;  // warp n-offset in tile
    const int g = lane >> 2;         // groupID (0..7)
    const int t = lane & 3;          // threadID_in_group (0..3)

    const int m0 = blockIdx.y * 128;
    const int n0 = blockIdx.x * 128;

    float acc[2][8][4];
    #pragma unroll
    for (int i = 0; i < 2; i++)
        #pragma unroll
        for (int j = 0; j < 8; j++)
            #pragma unroll
            for (int r = 0; r < 4; r++) acc[i][j][r] = 0.0f;

    // ---- async stage of one k-slab into buffer `buf` ----
    auto stage = [&](int buf, int k0) {
        #pragma unroll
        for (int c = 0; c < 2; c++) {
            int e = c * 256 + tid;
            int row = e >> 2;
            int col4 = (e & 3) << 2;
            int ar = m0 + row; if (ar > M - 1) ar = M - 1;
            cp16(&As[buf][row][col4], A + (size_t)ar * lda + k0 + col4);
            int br = n0 + row; if (br > N - 1) br = N - 1;
            cp16(&Bs[buf][row][col4], B + (size_t)br * ldb + k0 + col4);
        }
    };

    const int KT = K / 16;
    stage(0, 0);
    cp_commit();

    for (int it = 0; it < KT; it++) {
        if (it + 1 < KT) {
            stage((it + 1) & 1, (it + 1) * 16);
            cp_commit();
            cp_wait1();
        } else {
            cp_wait0();
        }
        __syncthreads();

        const int buf = it & 1;
        #pragma unroll
        for (int kk = 0; kk < 16; kk += 8) {
            uint32_t af[2][4];
            uint32_t bf[8][2];
            #pragma unroll
            for (int i = 0; i < 2; i++) {
                int r = wm + i * 16;
                float a0 = As[buf][r + g][kk + t];
                float a1 = As[buf][r + g + 8][kk + t];
                float a2 = As[buf][r + g][kk + t + 4];
                float a3 = As[buf][r + g + 8][kk + t + 4];
                if (CVT_IN) {
                    af[i][0] = f2tf32(a0); af[i][1] = f2tf32(a1);
                    af[i][2] = f2tf32(a2); af[i][3] = f2tf32(a3);
                } else {
                    af[i][0] = __float_as_uint(a0); af[i][1] = __float_as_uint(a1);
                    af[i][2] = __float_as_uint(a2); af[i][3] = __float_as_uint(a3);
                }
            }
            #pragma unroll
            for (int j = 0; j < 8; j++) {
                float b0 = Bs[buf][wn + j * 8 + g][kk + t];
                float b1 = Bs[buf][wn + j * 8 + g][kk + t + 4];
                if (CVT_IN) {
                    bf[j][0] = f2tf32(b0); bf[j][1] = f2tf32(b1);
                } else {
                    bf[j][0] = __float_as_uint(b0); bf[j][1] = __float_as_uint(b1);
                }
            }
            #pragma unroll
            for (int i = 0; i < 2; i++)
                #pragma unroll
                for (int j = 0; j < 8; j++)
                    mma_tf32(acc[i][j], af[i], bf[j]);
        }
        __syncthreads();
    }

    // ---- epilogue ----
    #pragma unroll
    for (int i = 0; i < 2; i++) {
        int r0 = m0 + wm + i * 16 + g;
        #pragma unroll
        for (int j = 0; j < 8; j++) {
            int col = n0 + wn + j * 8 + 2 * t;
            if (col < N) {  // N % 8 == 0 -> pair fully in-bounds
                float v[4];
                #pragma unroll
                for (int r = 0; r < 4; r++) {
                    float x = acc[i][j][r];
                    if (EXP_EPI) x = __expf(x - 1.0f);
                    if (ROUND_OUT) x = tf32r(x);
                    v[r] = x;
                }
                if (r0 < M)
                    *(float2*)(C + (size_t)r0 * ldc + col) = make_float2(v[0], v[1]);
                if (r0 + 8 < M)
                    *(float2*)(C + (size_t)(r0 + 8) * ldc + col) = make_float2(v[2], v[3]);
            }
        }
    }
}

// ---------------------------------------------------------------------------
// Launch
// ---------------------------------------------------------------------------
extern "C" void kernel_launch(void* const* d_in, const int* in_sizes, int n_in,
                              void* d_out, int out_size) {
    const float* query = (const float*)d_in[0];
    const float* key   = (const float*)d_in[1];
    const float* prox  = (const float*)d_in[2];
    const int*   cls   = (const int*)d_in[3];

    const int Q = in_sizes[0] / D_DIM;   // 4096
    const int S = in_sizes[1] / D_DIM;   // 8192
    const int C = in_sizes[2] / D_DIM;   // 1000
    float* out = (float*)d_out;

    float *qn, *kn, *attn, *a2, *gram;
    cudaGetSymbolAddress((void**)&qn,   g_qn);
    cudaGetSymbolAddress((void**)&kn,   g_kn);
    cudaGetSymbolAddress((void**)&attn, g_attn);
    cudaGetSymbolAddress((void**)&a2,   g_a2);
    cudaGetSymbolAddress((void**)&gram, g_gram);

    cls_convert_kernel<<<(S + 255) / 256, 256>>>(cls, S);
    l2norm_kernel<<<Q, 256>>>(query, qn);
    l2norm_kernel<<<S, 256>>>(key, kn);

    // G1: attn[Q,S] = exp(qn @ kn^T - 1)   (inputs pre-rounded tf32)
    {
        dim3 grid(S / 128, Q / 128);
        gemm_tf32_nt<true, false, false><<<grid, 256>>>(
            qn, kn, attn, Q, S, D_DIM, D_DIM, D_DIM, S);
    }

    // Gram: G[c',c] = P[c'] . P[c]   (raw fp32 -> CVT_IN; output tf32-rounded)
    {
        dim3 grid((C + 127) / 128, (C + 127) / 128);
        gemm_tf32_nt<false, true, true><<<grid, 256>>>(
            prox, prox, gram, C, C, D_DIM, D_DIM, D_DIM, CPAD);
    }

    // A2[q,c] = sum over supports of class c of attn[q,s]
    a2_kernel<<<Q, 256>>>(attn, a2, S);

    // logits[Q,C] = A2 @ Gram^T  (both operands pre-rounded tf32)
    {
        dim3 grid((C + 127) / 128, Q / 128);
        gemm_tf32_nt<false, false, false><<<grid, 256>>>(
            a2, gram, out, Q, C, CPAD, CPAD, CPAD, C);
    }
}

// round 4
// speedup vs baseline: 5.3065x; 1.3087x over previous
#include <cuda_runtime.h>
#include <cuda_bf16.h>
#include <math.h>
#include <stdint.h>

#define D_DIM 512
#define MAXQ 4096
#define MAXS 8192
#define CPAD 1024
#define NCLS 1000

// ---------------------------------------------------------------------------
// Static scratch
// ---------------------------------------------------------------------------
__device__ __nv_bfloat16 g_qnh[(size_t)MAXQ * D_DIM];   // normalized queries, bf16
__device__ __nv_bfloat16 g_knh[(size_t)MAXS * D_DIM];   // normalized keys, bf16
__device__ float g_attn[(size_t)MAXQ * MAXS];           // exp kernel, fp32
__device__ float g_a2[(size_t)MAXQ * CPAD];             // class-bucketed sums (tf32)
__device__ float g_gram[(size_t)NCLS * CPAD];           // P @ P^T (tf32); pad cols 0
__device__ int   g_cls32[MAXS];

// ---------------------------------------------------------------------------
// Helpers (portable sm_80+ PTX only — toolchain targets plain sm_100)
// ---------------------------------------------------------------------------
__device__ __forceinline__ uint32_t smem_u32(const void* p) {
    uint32_t a;
    asm("{ .reg .u64 t; cvta.to.shared.u64 t, %1; cvt.u32.u64 %0, t; }" : "=r"(a) : "l"(p));
    return a;
}
__device__ __forceinline__ uint32_t f2tf32(float x) {
    uint32_t u;
    asm("cvt.rna.tf32.f32 %0, %1;" : "=r"(u) : "f"(x));
    return u;
}
__device__ __forceinline__ float tf32r(float x) { return __uint_as_float(f2tf32(x)); }

__device__ __forceinline__ void cp16(uint32_t dst_smem, const void* src) {
    asm volatile("cp.async.cg.shared.global [%0], [%1], 16;\n" :: "r"(dst_smem), "l"(src));
}
__device__ __forceinline__ void cp_commit() { asm volatile("cp.async.commit_group;\n" ::: "memory"); }
__device__ __forceinline__ void cp_wait0() { asm volatile("cp.async.wait_group 0;\n" ::: "memory"); }
__device__ __forceinline__ void cp_wait1() { asm volatile("cp.async.wait_group 1;\n" ::: "memory"); }

__device__ __forceinline__ void mma_bf16(float* c, const uint32_t* a, const uint32_t* b) {
    asm volatile(
        "mma.sync.aligned.m16n8k16.row.col.f32.bf16.bf16.f32 "
        "{%0,%1,%2,%3}, {%4,%5,%6,%7}, {%8,%9}, {%0,%1,%2,%3};\n"
        : "+f"(c[0]), "+f"(c[1]), "+f"(c[2]), "+f"(c[3])
        : "r"(a[0]), "r"(a[1]), "r"(a[2]), "r"(a[3]), "r"(b[0]), "r"(b[1]));
}
__device__ __forceinline__ void mma_tf32(float* c, const uint32_t* a, const uint32_t* b) {
    asm volatile(
        "mma.sync.aligned.m16n8k8.row.col.f32.tf32.tf32.f32 "
        "{%0,%1,%2,%3}, {%4,%5,%6,%7}, {%8,%9}, {%0,%1,%2,%3};\n"
        : "+f"(c[0]), "+f"(c[1]), "+f"(c[2]), "+f"(c[3])
        : "r"(a[0]), "r"(a[1]), "r"(a[2]), "r"(a[3]), "r"(b[0]), "r"(b[1]));
}

// ---------------------------------------------------------------------------
// Class id convert (int64/int32 auto-detect)
// ---------------------------------------------------------------------------
__global__ void cls_convert_kernel(const int* __restrict__ raw, int S) {
    __shared__ int is64s;
    if (threadIdx.x == 0) {
        int is64 = 1;
        int nw = S < 64 ? S : 64;
        for (int i = 1; i < nw; i += 2)
            if (raw[i] != 0) { is64 = 0; break; }
        is64s = is64;
    }
    __syncthreads();
    int s = blockIdx.x * blockDim.x + threadIdx.x;
    if (s < S)
        g_cls32[s] = is64s ? (int)((const long long*)raw)[s] : raw[s];
}

// ---------------------------------------------------------------------------
// L2 normalize rows -> bf16 (RN)
// ---------------------------------------------------------------------------
__global__ void l2norm_bf16_kernel(const float* __restrict__ in, __nv_bfloat16* __restrict__ out) {
    int row = blockIdx.x;
    const float* x = in + (size_t)row * D_DIM;
    __nv_bfloat16* y = out + (size_t)row * D_DIM;
    int tid = threadIdx.x;

    float v0 = x[tid];
    float v1 = x[tid + 256];
    float s = v0 * v0 + v1 * v1;
    #pragma unroll
    for (int o = 16; o > 0; o >>= 1) s += __shfl_xor_sync(0xffffffffu, s, o);

    __shared__ float ws[8];
    if ((tid & 31) == 0) ws[tid >> 5] = s;
    __syncthreads();
    if (tid < 8) {
        float t = ws[tid];
        #pragma unroll
        for (int o = 4; o > 0; o >>= 1) t += __shfl_xor_sync(0xffu, t, o);
        if (tid == 0) ws[0] = t;
    }
    __syncthreads();

    float inv = 1.0f / fmaxf(sqrtf(ws[0]), 1e-12f);
    y[tid] = __float2bfloat16_rn(v0 * inv);
    y[tid + 256] = __float2bfloat16_rn(v1 * inv);
}

// ---------------------------------------------------------------------------
// G1: attn[Q,S] = exp(A @ B^T - 1), bf16 mma.sync m16n8k16.
// 128x128 tile, BK=32, 256 threads (8 warps, 32m x 64n), cp.async double buffer.
// Rows padded to 40 bf16 (20 words): g*20+t is a permutation mod 32 ->
// conflict-free fragment loads. M, N multiples of 128; K multiple of 32.
// ---------------------------------------------------------------------------
__global__ __launch_bounds__(256, 2)
void g1_bf16_kernel(const __nv_bfloat16* __restrict__ A, const __nv_bfloat16* __restrict__ B,
                    float* __restrict__ C, int M, int N, int K) {
    __shared__ __nv_bfloat16 As[2][128][40];
    __shared__ __nv_bfloat16 Bs[2][128][40];

    const int tid = threadIdx.x;
    const int lane = tid & 31;
    const int wid = tid >> 5;
    const int wm = (wid & 3) * 32;
    const int wn = (wid >> 2) * 64;
    const int g = lane >> 2;
    const int t = lane & 3;
    const int m0 = blockIdx.y * 128;
    const int n0 = blockIdx.x * 128;

    float acc[2][8][4];
    #pragma unroll
    for (int i = 0; i < 2; i++)
        #pragma unroll
        for (int j = 0; j < 8; j++)
            #pragma unroll
            for (int r = 0; r < 4; r++) acc[i][j][r] = 0.0f;

    auto stage = [&](int buf, int k0) {
        #pragma unroll
        for (int c = 0; c < 2; c++) {
            int e = c * 256 + tid;
            int row = e >> 2;
            int col = (e & 3) * 8;   // bf16 units; 16B per cp
            cp16(smem_u32(&As[buf][row][col]), A + (size_t)(m0 + row) * K + k0 + col);
            cp16(smem_u32(&Bs[buf][row][col]), B + (size_t)(n0 + row) * K + k0 + col);
        }
        cp_commit();
    };

    const int KT = K / 32;
    stage(0, 0);

    for (int it = 0; it < KT; it++) {
        if (it + 1 < KT) {
            stage((it + 1) & 1, (it + 1) * 32);
            cp_wait1();
        } else {
            cp_wait0();
        }
        __syncthreads();

        const int buf = it & 1;
        #pragma unroll
        for (int kk = 0; kk < 2; kk++) {           // two k16 halves of BK=32
            const int plo = (kk * 8 + t) * 2;      // bf16 col of low k-pair
            const int phi = (kk * 8 + t + 4) * 2;  // bf16 col of high k-pair
            uint32_t af[2][4];
            uint32_t bfr[8][2];
            #pragma unroll
            for (int i = 0; i < 2; i++) {
                int r = wm + i * 16;
                af[i][0] = *(const uint32_t*)&As[buf][r + g][plo];
                af[i][1] = *(const uint32_t*)&As[buf][r + g + 8][plo];
                af[i][2] = *(const uint32_t*)&As[buf][r + g][phi];
                af[i][3] = *(const uint32_t*)&As[buf][r + g + 8][phi];
            }
            #pragma unroll
            for (int j = 0; j < 8; j++) {
                bfr[j][0] = *(const uint32_t*)&Bs[buf][wn + j * 8 + g][plo];
                bfr[j][1] = *(const uint32_t*)&Bs[buf][wn + j * 8 + g][phi];
            }
            #pragma unroll
            for (int i = 0; i < 2; i++)
                #pragma unroll
                for (int j = 0; j < 8; j++)
                    mma_bf16(acc[i][j], af[i], bfr[j]);
        }
        __syncthreads();
    }

    // epilogue: exp(x - 1), float2 stores (M, N multiples of 128 -> no guards)
    #pragma unroll
    for (int i = 0; i < 2; i++) {
        int r0 = m0 + wm + i * 16 + g;
        #pragma unroll
        for (int j = 0; j < 8; j++) {
            int col = n0 + wn + j * 8 + 2 * t;
            float2 v0, v1;
            v0.x = __expf(acc[i][j][0] - 1.0f);
            v0.y = __expf(acc[i][j][1] - 1.0f);
            v1.x = __expf(acc[i][j][2] - 1.0f);
            v1.y = __expf(acc[i][j][3] - 1.0f);
            *(float2*)(C + (size_t)r0 * N + col) = v0;
            *(float2*)(C + (size_t)(r0 + 8) * N + col) = v1;
        }
    }
}

// ---------------------------------------------------------------------------
// A2[q,c] = sum_{s: cls_s == c} attn[q,s]  (deterministic u64 fixed-point)
// ---------------------------------------------------------------------------
__global__ void a2_kernel(const float* __restrict__ attn, float* __restrict__ A2, int S) {
    __shared__ unsigned long long bins[CPAD];
    int q = blockIdx.x;
    int tid = threadIdx.x;
    for (int c = tid; c < CPAD; c += 256) bins[c] = 0ULL;
    __syncthreads();

    const float4* row = (const float4*)(attn + (size_t)q * S);
    const int4* cls4 = (const int4*)g_cls32;
    const float SCALE_UP = 70368744177664.0f;  // 2^46
    for (int s4 = tid; s4 < S / 4; s4 += 256) {
        float4 v = row[s4];
        int4 c = cls4[s4];
        atomicAdd(&bins[c.x], (unsigned long long)(v.x * SCALE_UP));
        atomicAdd(&bins[c.y], (unsigned long long)(v.y * SCALE_UP));
        atomicAdd(&bins[c.z], (unsigned long long)(v.z * SCALE_UP));
        atomicAdd(&bins[c.w], (unsigned long long)(v.w * SCALE_UP));
    }
    __syncthreads();

    const float SCALE_DN = 1.0f / 70368744177664.0f;
    for (int c = tid; c < CPAD; c += 256) {
        float v = (c < NCLS) ? (float)bins[c] * SCALE_DN : 0.0f;
        A2[(size_t)q * CPAD + c] = tf32r(v);
    }
}

// ---------------------------------------------------------------------------
// tf32 NT GEMM (validated round 2) for Gram and G3
// ---------------------------------------------------------------------------
template <bool CVT_IN, bool ROUND_OUT>
__global__ __launch_bounds__(256, 2)
void gemm_tf32_nt(const float* __restrict__ A, const float* __restrict__ B,
                  float* __restrict__ C, int M, int N, int K,
                  int lda, int ldb, int ldc) {
    __shared__ float As[2][128][20];
    __shared__ float Bs[2][128][20];

    const int tid = threadIdx.x;
    const int lane = tid & 31;
    const int wid = tid >> 5;
    const int wm = (wid & 3) * 32;
    const int wn = (wid >> 2) * 64;
    const int g = lane >> 2;
    const int t = lane & 3;
    const int m0 = blockIdx.y * 128;
    const int n0 = blockIdx.x * 128;

    float acc[2][8][4];
    #pragma unroll
    for (int i = 0; i < 2; i++)
        #pragma unroll
        for (int j = 0; j < 8; j++)
            #pragma unroll
            for (int r = 0; r < 4; r++) acc[i][j][r] = 0.0f;

    auto stage = [&](int buf, int k0) {
        #pragma unroll
        for (int c = 0; c < 2; c++) {
            int e = c * 256 + tid;
            int row = e >> 2;
            int col4 = (e & 3) << 2;
            int ar = m0 + row; if (ar > M - 1) ar = M - 1;
            cp16(smem_u32(&As[buf][row][col4]), A + (size_t)ar * lda + k0 + col4);
            int br = n0 + row; if (br > N - 1) br = N - 1;
            cp16(smem_u32(&Bs[buf][row][col4]), B + (size_t)br * ldb + k0 + col4);
        }
        cp_commit();
    };

    const int KT = K / 16;
    stage(0, 0);

    for (int it = 0; it < KT; it++) {
        if (it + 1 < KT) {
            stage((it + 1) & 1, (it + 1) * 16);
            cp_wait1();
        } else {
            cp_wait0();
        }
        __syncthreads();

        const int buf = it & 1;
        #pragma unroll
        for (int kk = 0; kk < 16; kk += 8) {
            uint32_t af[2][4];
            uint32_t bfr[8][2];
            #pragma unroll
            for (int i = 0; i < 2; i++) {
                int r = wm + i * 16;
                float a0 = As[buf][r + g][kk + t];
                float a1 = As[buf][r + g + 8][kk + t];
                float a2 = As[buf][r + g][kk + t + 4];
                float a3 = As[buf][r + g + 8][kk + t + 4];
                if (CVT_IN) {
                    af[i][0] = f2tf32(a0); af[i][1] = f2tf32(a1);
                    af[i][2] = f2tf32(a2); af[i][3] = f2tf32(a3);
                } else {
                    af[i][0] = __float_as_uint(a0); af[i][1] = __float_as_uint(a1);
                    af[i][2] = __float_as_uint(a2); af[i][3] = __float_as_uint(a3);
                }
            }
            #pragma unroll
            for (int j = 0; j < 8; j++) {
                float b0 = Bs[buf][wn + j * 8 + g][kk + t];
                float b1 = Bs[buf][wn + j * 8 + g][kk + t + 4];
                if (CVT_IN) { bfr[j][0] = f2tf32(b0); bfr[j][1] = f2tf32(b1); }
                else { bfr[j][0] = __float_as_uint(b0); bfr[j][1] = __float_as_uint(b1); }
            }
            #pragma unroll
            for (int i = 0; i < 2; i++)
                #pragma unroll
                for (int j = 0; j < 8; j++)
                    mma_tf32(acc[i][j], af[i], bfr[j]);
        }
        __syncthreads();
    }

    #pragma unroll
    for (int i = 0; i < 2; i++) {
        int r0 = m0 + wm + i * 16 + g;
        #pragma unroll
        for (int j = 0; j < 8; j++) {
            int col = n0 + wn + j * 8 + 2 * t;
            if (col < N) {
                float v[4];
                #pragma unroll
                for (int r = 0; r < 4; r++) {
                    float x = acc[i][j][r];
                    if (ROUND_OUT) x = tf32r(x);
                    v[r] = x;
                }
                if (r0 < M)
                    *(float2*)(C + (size_t)r0 * ldc + col) = make_float2(v[0], v[1]);
                if (r0 + 8 < M)
                    *(float2*)(C + (size_t)(r0 + 8) * ldc + col) = make_float2(v[2], v[3]);
            }
        }
    }
}

// ---------------------------------------------------------------------------
// Launch
// ---------------------------------------------------------------------------
extern "C" void kernel_launch(void* const* d_in, const int* in_sizes, int n_in,
                              void* d_out, int out_size) {
    const float* query = (const float*)d_in[0];
    const float* key   = (const float*)d_in[1];
    const float* prox  = (const float*)d_in[2];
    const int*   cls   = (const int*)d_in[3];

    const int Q = in_sizes[0] / D_DIM;   // 4096
    const int S = in_sizes[1] / D_DIM;   // 8192
    const int C = in_sizes[2] / D_DIM;   // 1000
    float* out = (float*)d_out;

    __nv_bfloat16 *qnh, *knh;
    float *attn, *a2, *gram;
    cudaGetSymbolAddress((void**)&qnh,  g_qnh);
    cudaGetSymbolAddress((void**)&knh,  g_knh);
    cudaGetSymbolAddress((void**)&attn, g_attn);
    cudaGetSymbolAddress((void**)&a2,   g_a2);
    cudaGetSymbolAddress((void**)&gram, g_gram);

    cls_convert_kernel<<<(S + 255) / 256, 256>>>(cls, S);
    l2norm_bf16_kernel<<<Q, 256>>>(query, qnh);
    l2norm_bf16_kernel<<<S, 256>>>(key, knh);

    // G1: attn = exp(qn @ kn^T - 1), bf16 m16n8k16
    {
        dim3 grid(S / 128, Q / 128);
        g1_bf16_kernel<<<grid, 256>>>(qnh, knh, attn, Q, S, D_DIM);
    }

    // Gram: G[c',c] = P[c'] . P[c]  (tf32, CVT at load, tf32-rounded out)
    {
        dim3 grid((C + 127) / 128, (C + 127) / 128);
        gemm_tf32_nt<true, true><<<grid, 256>>>(prox, prox, gram, C, C, D_DIM, D_DIM, D_DIM, CPAD);
    }

    // A2
    a2_kernel<<<Q, 256>>>(attn, a2, S);

    // logits = A2 @ Gram^T (tf32)
    {
        dim3 grid((C + 127) / 128, Q / 128);
        gemm_tf32_nt<false, false><<<grid, 256>>>(a2, gram, out, Q, C, CPAD, CPAD, CPAD, C);
    }
}

// round 5
// speedup vs baseline: 5.5506x; 1.0460x over previous
#include <cuda_runtime.h>
#include <cuda_bf16.h>
#include <math.h>
#include <stdint.h>

#define D_DIM 512
#define MAXQ 4096
#define MAXS 8192
#define CPAD 1024
#define NCLS 1000

// ---------------------------------------------------------------------------
// Static scratch
// ---------------------------------------------------------------------------
__device__ __nv_bfloat16 g_qnh[(size_t)MAXQ * D_DIM];   // normalized queries, bf16
__device__ __nv_bfloat16 g_knh[(size_t)MAXS * D_DIM];   // normalized keys, bf16
__device__ __nv_bfloat16 g_attn[(size_t)MAXQ * MAXS];   // exp kernel, bf16
__device__ float g_a2[(size_t)MAXQ * CPAD];             // class-bucketed sums (tf32)
__device__ float g_gram[(size_t)NCLS * CPAD];           // P @ P^T (tf32); pad cols 0
__device__ int   g_cls32[MAXS];

// ---------------------------------------------------------------------------
// Helpers (portable sm_80+ PTX only — toolchain targets plain sm_100)
// ---------------------------------------------------------------------------
__device__ __forceinline__ uint32_t smem_u32(const void* p) {
    uint32_t a;
    asm("{ .reg .u64 t; cvta.to.shared.u64 t, %1; cvt.u32.u64 %0, t; }" : "=r"(a) : "l"(p));
    return a;
}
__device__ __forceinline__ uint32_t f2tf32(float x) {
    uint32_t u;
    asm("cvt.rna.tf32.f32 %0, %1;" : "=r"(u) : "f"(x));
    return u;
}
__device__ __forceinline__ float tf32r(float x) { return __uint_as_float(f2tf32(x)); }

__device__ __forceinline__ void cp16(uint32_t dst_smem, const void* src) {
    asm volatile("cp.async.cg.shared.global [%0], [%1], 16;\n" :: "r"(dst_smem), "l"(src));
}
__device__ __forceinline__ void cp_commit() { asm volatile("cp.async.commit_group;\n" ::: "memory"); }
__device__ __forceinline__ void cp_wait0() { asm volatile("cp.async.wait_group 0;\n" ::: "memory"); }
__device__ __forceinline__ void cp_wait1() { asm volatile("cp.async.wait_group 1;\n" ::: "memory"); }
__device__ __forceinline__ void cp_wait2() { asm volatile("cp.async.wait_group 2;\n" ::: "memory"); }

__device__ __forceinline__ void ldm_x4(uint32_t* r, uint32_t addr) {
    asm volatile("ldmatrix.sync.aligned.m8n8.x4.shared.b16 {%0,%1,%2,%3}, [%4];"
                 : "=r"(r[0]), "=r"(r[1]), "=r"(r[2]), "=r"(r[3]) : "r"(addr));
}

__device__ __forceinline__ void mma_bf16(float* c, const uint32_t* a, const uint32_t* b) {
    asm volatile(
        "mma.sync.aligned.m16n8k16.row.col.f32.bf16.bf16.f32 "
        "{%0,%1,%2,%3}, {%4,%5,%6,%7}, {%8,%9}, {%0,%1,%2,%3};\n"
        : "+f"(c[0]), "+f"(c[1]), "+f"(c[2]), "+f"(c[3])
        : "r"(a[0]), "r"(a[1]), "r"(a[2]), "r"(a[3]), "r"(b[0]), "r"(b[1]));
}
__device__ __forceinline__ void mma_tf32(float* c, const uint32_t* a, const uint32_t* b) {
    asm volatile(
        "mma.sync.aligned.m16n8k8.row.col.f32.tf32.tf32.f32 "
        "{%0,%1,%2,%3}, {%4,%5,%6,%7}, {%8,%9}, {%0,%1,%2,%3};\n"
        : "+f"(c[0]), "+f"(c[1]), "+f"(c[2]), "+f"(c[3])
        : "r"(a[0]), "r"(a[1]), "r"(a[2]), "r"(a[3]), "r"(b[0]), "r"(b[1]));
}

// ---------------------------------------------------------------------------
// Class id convert (int64/int32 auto-detect)
// ---------------------------------------------------------------------------
__global__ void cls_convert_kernel(const int* __restrict__ raw, int S) {
    __shared__ int is64s;
    if (threadIdx.x == 0) {
        int is64 = 1;
        int nw = S < 64 ? S : 64;
        for (int i = 1; i < nw; i += 2)
            if (raw[i] != 0) { is64 = 0; break; }
        is64s = is64;
    }
    __syncthreads();
    int s = blockIdx.x * blockDim.x + threadIdx.x;
    if (s < S)
        g_cls32[s] = is64s ? (int)((const long long*)raw)[s] : raw[s];
}

// ---------------------------------------------------------------------------
// L2 normalize rows -> bf16 (RN)
// ---------------------------------------------------------------------------
__global__ void l2norm_bf16_kernel(const float* __restrict__ in, __nv_bfloat16* __restrict__ out) {
    int row = blockIdx.x;
    const float* x = in + (size_t)row * D_DIM;
    __nv_bfloat16* y = out + (size_t)row * D_DIM;
    int tid = threadIdx.x;

    float v0 = x[tid];
    float v1 = x[tid + 256];
    float s = v0 * v0 + v1 * v1;
    #pragma unroll
    for (int o = 16; o > 0; o >>= 1) s += __shfl_xor_sync(0xffffffffu, s, o);

    __shared__ float ws[8];
    if ((tid & 31) == 0) ws[tid >> 5] = s;
    __syncthreads();
    if (tid < 8) {
        float t = ws[tid];
        #pragma unroll
        for (int o = 4; o > 0; o >>= 1) t += __shfl_xor_sync(0xffu, t, o);
        if (tid == 0) ws[0] = t;
    }
    __syncthreads();

    float inv = 1.0f / fmaxf(sqrtf(ws[0]), 1e-12f);
    y[tid] = __float2bfloat16_rn(v0 * inv);
    y[tid + 256] = __float2bfloat16_rn(v1 * inv);
}

// ---------------------------------------------------------------------------
// G1: attn[Q,S] = exp(A @ B^T - 1) in bf16.
// bf16 m16n8k16 via ldmatrix.x4, 128x128 tile, BK=32, 3-stage cp.async.
// 8 warps of 32m x 64n. Smem rows padded to 40 bf16 (80B): every ldmatrix
// 8-address phase hits distinct 16B banks. M,N mult of 128; K mult of 32.
// ---------------------------------------------------------------------------
#define G1_PITCH 40
#define G1_TILE_ELEMS (128 * G1_PITCH)                 // 5120 bf16 per tile
#define G1_STAGE_BYTES (G1_TILE_ELEMS * 2)             // 10240 B
#define G1_SMEM (6 * G1_STAGE_BYTES)                   // 3 stages x (A+B) = 61440 B

__global__ __launch_bounds__(256, 2)
void g1_bf16_kernel(const __nv_bfloat16* __restrict__ A, const __nv_bfloat16* __restrict__ B,
                    __nv_bfloat16* __restrict__ C, int M, int N, int K) {
    extern __shared__ __nv_bfloat16 smem[];
    const uint32_t sb = smem_u32(smem);

    const int tid = threadIdx.x;
    const int lane = tid & 31;
    const int wid = tid >> 5;
    const int wm = (wid & 3) * 32;
    const int wn = (wid >> 2) * 64;
    const int g = lane >> 2;
    const int t = lane & 3;
    const int lr = lane & 7;
    const int lb3 = (lane >> 3) & 1;
    const int lb4 = (lane >> 4) & 1;
    const int m0 = blockIdx.y * 128;
    const int n0 = blockIdx.x * 128;

    float acc[2][8][4];
    #pragma unroll
    for (int i = 0; i < 2; i++)
        #pragma unroll
        for (int j = 0; j < 8; j++)
            #pragma unroll
            for (int r = 0; r < 4; r++) acc[i][j][r] = 0.0f;

    // staging: per stage, A tile 128x32 bf16 + B tile 128x32 bf16
    const int srow = tid >> 2;           // 0..63
    const int scol = (tid & 3) * 8;      // bf16 col: 0,8,16,24
    auto stage = [&](int s, int k0) {
        uint32_t abase = sb + s * (uint32_t)G1_STAGE_BYTES * 2;          // A stages interleave? no:
        // layout: [A0 A1 A2 B0 B1 B2]
        abase = sb + s * (uint32_t)G1_STAGE_BYTES;
        uint32_t bbase = sb + (uint32_t)(3 * G1_STAGE_BYTES) + s * (uint32_t)G1_STAGE_BYTES;
        #pragma unroll
        for (int h = 0; h < 2; h++) {
            int row = srow + h * 64;
            cp16(abase + (row * G1_PITCH + scol) * 2, A + (size_t)(m0 + row) * K + k0 + scol);
            cp16(bbase + (row * G1_PITCH + scol) * 2, B + (size_t)(n0 + row) * K + k0 + scol);
        }
        cp_commit();
    };

    const int KT = K / 32;
    stage(0, 0);
    stage(1, 32);

    for (int it = 0; it < KT; it++) {
        if (it + 2 < KT) stage((it + 2) % 3, (it + 2) * 32);
        const int rem = KT - 1 - it;
        if (rem >= 2) cp_wait2();
        else if (rem == 1) cp_wait1();
        else cp_wait0();
        __syncthreads();

        const int buf = it % 3;
        const uint32_t abase = sb + buf * (uint32_t)G1_STAGE_BYTES;
        const uint32_t bbase = sb + (uint32_t)(3 * G1_STAGE_BYTES) + buf * (uint32_t)G1_STAGE_BYTES;

        #pragma unroll
        for (int kk = 0; kk < 2; kk++) {
            uint32_t af[2][4];
            #pragma unroll
            for (int i = 0; i < 2; i++) {
                int row = wm + i * 16 + lb3 * 8 + lr;
                int col = kk * 16 + lb4 * 8;
                ldm_x4(af[i], abase + (row * G1_PITCH + col) * 2);
            }
            uint32_t bf[4][4];
            #pragma unroll
            for (int jp = 0; jp < 4; jp++) {
                int row = wn + jp * 16 + lb4 * 8 + lr;
                int col = kk * 16 + lb3 * 8;
                ldm_x4(bf[jp], bbase + (row * G1_PITCH + col) * 2);
            }
            #pragma unroll
            for (int i = 0; i < 2; i++)
                #pragma unroll
                for (int jp = 0; jp < 4; jp++) {
                    mma_bf16(acc[i][2 * jp],     af[i], &bf[jp][0]);
                    mma_bf16(acc[i][2 * jp + 1], af[i], &bf[jp][2]);
                }
        }
        __syncthreads();
    }

    // epilogue: exp(x-1) -> bf16x2 stores
    #pragma unroll
    for (int i = 0; i < 2; i++) {
        int r0 = m0 + wm + i * 16 + g;
        #pragma unroll
        for (int j = 0; j < 8; j++) {
            int col = n0 + wn + j * 8 + 2 * t;
            __nv_bfloat162 p0 = __floats2bfloat162_rn(
                __expf(acc[i][j][0] - 1.0f), __expf(acc[i][j][1] - 1.0f));
            __nv_bfloat162 p1 = __floats2bfloat162_rn(
                __expf(acc[i][j][2] - 1.0f), __expf(acc[i][j][3] - 1.0f));
            *(__nv_bfloat162*)(C + (size_t)r0 * N + col) = p0;
            *(__nv_bfloat162*)(C + (size_t)(r0 + 8) * N + col) = p1;
        }
    }
}

// ---------------------------------------------------------------------------
// A2[q,c] = sum_{s: cls_s == c} attn[q,s]  (deterministic u64 fixed-point)
// attn is bf16 now; vectorized 8-wide reads.
// ---------------------------------------------------------------------------
__global__ void a2_kernel(const __nv_bfloat16* __restrict__ attn, float* __restrict__ A2, int S) {
    __shared__ unsigned long long bins[CPAD];
    int q = blockIdx.x;
    int tid = threadIdx.x;
    for (int c = tid; c < CPAD; c += 256) bins[c] = 0ULL;
    __syncthreads();

    const uint4* row = (const uint4*)(attn + (size_t)q * S);
    const int4* cls4 = (const int4*)g_cls32;
    const float SCALE_UP = 70368744177664.0f;  // 2^46
    for (int s8 = tid; s8 < S / 8; s8 += 256) {
        uint4 v = row[s8];
        int4 c0 = cls4[s8 * 2];
        int4 c1 = cls4[s8 * 2 + 1];
        __nv_bfloat162 h0 = *(__nv_bfloat162*)&v.x;
        __nv_bfloat162 h1 = *(__nv_bfloat162*)&v.y;
        __nv_bfloat162 h2 = *(__nv_bfloat162*)&v.z;
        __nv_bfloat162 h3 = *(__nv_bfloat162*)&v.w;
        atomicAdd(&bins[c0.x], (unsigned long long)(__low2float(h0)  * SCALE_UP));
        atomicAdd(&bins[c0.y], (unsigned long long)(__high2float(h0) * SCALE_UP));
        atomicAdd(&bins[c0.z], (unsigned long long)(__low2float(h1)  * SCALE_UP));
        atomicAdd(&bins[c0.w], (unsigned long long)(__high2float(h1) * SCALE_UP));
        atomicAdd(&bins[c1.x], (unsigned long long)(__low2float(h2)  * SCALE_UP));
        atomicAdd(&bins[c1.y], (unsigned long long)(__high2float(h2) * SCALE_UP));
        atomicAdd(&bins[c1.z], (unsigned long long)(__low2float(h3)  * SCALE_UP));
        atomicAdd(&bins[c1.w], (unsigned long long)(__high2float(h3) * SCALE_UP));
    }
    __syncthreads();

    const float SCALE_DN = 1.0f / 70368744177664.0f;
    for (int c = tid; c < CPAD; c += 256) {
        float v = (c < NCLS) ? (float)bins[c] * SCALE_DN : 0.0f;
        A2[(size_t)q * CPAD + c] = tf32r(v);
    }
}

// ---------------------------------------------------------------------------
// tf32 NT GEMM (validated) for Gram and G3
// ---------------------------------------------------------------------------
template <bool CVT_IN, bool ROUND_OUT>
__global__ __launch_bounds__(256, 2)
void gemm_tf32_nt(const float* __restrict__ A, const float* __restrict__ B,
                  float* __restrict__ C, int M, int N, int K,
                  int lda, int ldb, int ldc) {
    __shared__ float As[2][128][20];
    __shared__ float Bs[2][128][20];

    const int tid = threadIdx.x;
    const int lane = tid & 31;
    const int wid = tid >> 5;
    const int wm = (wid & 3) * 32;
    const int wn = (wid >> 2) * 64;
    const int g = lane >> 2;
    const int t = lane & 3;
    const int m0 = blockIdx.y * 128;
    const int n0 = blockIdx.x * 128;

    float acc[2][8][4];
    #pragma unroll
    for (int i = 0; i < 2; i++)
        #pragma unroll
        for (int j = 0; j < 8; j++)
            #pragma unroll
            for (int r = 0; r < 4; r++) acc[i][j][r] = 0.0f;

    auto stage = [&](int buf, int k0) {
        #pragma unroll
        for (int c = 0; c < 2; c++) {
            int e = c * 256 + tid;
            int row = e >> 2;
            int col4 = (e & 3) << 2;
            int ar = m0 + row; if (ar > M - 1) ar = M - 1;
            cp16(smem_u32(&As[buf][row][col4]), A + (size_t)ar * lda + k0 + col4);
            int br = n0 + row; if (br > N - 1) br = N - 1;
            cp16(smem_u32(&Bs[buf][row][col4]), B + (size_t)br * ldb + k0 + col4);
        }
        cp_commit();
    };

    const int KT = K / 16;
    stage(0, 0);

    for (int it = 0; it < KT; it++) {
        if (it + 1 < KT) {
            stage((it + 1) & 1, (it + 1) * 16);
            cp_wait1();
        } else {
            cp_wait0();
        }
        __syncthreads();

        const int buf = it & 1;
        #pragma unroll
        for (int kk = 0; kk < 16; kk += 8) {
            uint32_t af[2][4];
            uint32_t bfr[8][2];
            #pragma unroll
            for (int i = 0; i < 2; i++) {
                int r = wm + i * 16;
                float a0 = As[buf][r + g][kk + t];
                float a1 = As[buf][r + g + 8][kk + t];
                float a2 = As[buf][r + g][kk + t + 4];
                float a3 = As[buf][r + g + 8][kk + t + 4];
                if (CVT_IN) {
                    af[i][0] = f2tf32(a0); af[i][1] = f2tf32(a1);
                    af[i][2] = f2tf32(a2); af[i][3] = f2tf32(a3);
                } else {
                    af[i][0] = __float_as_uint(a0); af[i][1] = __float_as_uint(a1);
                    af[i][2] = __float_as_uint(a2); af[i][3] = __float_as_uint(a3);
                }
            }
            #pragma unroll
            for (int j = 0; j < 8; j++) {
                float b0 = Bs[buf][wn + j * 8 + g][kk + t];
                float b1 = Bs[buf][wn + j * 8 + g][kk + t + 4];
                if (CVT_IN) { bfr[j][0] = f2tf32(b0); bfr[j][1] = f2tf32(b1); }
                else { bfr[j][0] = __float_as_uint(b0); bfr[j][1] = __float_as_uint(b1); }
            }
            #pragma unroll
            for (int i = 0; i < 2; i++)
                #pragma unroll
                for (int j = 0; j < 8; j++)
                    mma_tf32(acc[i][j], af[i], bfr[j]);
        }
        __syncthreads();
    }

    #pragma unroll
    for (int i = 0; i < 2; i++) {
        int r0 = m0 + wm + i * 16 + g;
        #pragma unroll
        for (int j = 0; j < 8; j++) {
            int col = n0 + wn + j * 8 + 2 * t;
            if (col < N) {
                float v[4];
                #pragma unroll
                for (int r = 0; r < 4; r++) {
                    float x = acc[i][j][r];
                    if (ROUND_OUT) x = tf32r(x);
                    v[r] = x;
                }
                if (r0 < M)
                    *(float2*)(C + (size_t)r0 * ldc + col) = make_float2(v[0], v[1]);
                if (r0 + 8 < M)
                    *(float2*)(C + (size_t)(r0 + 8) * ldc + col) = make_float2(v[2], v[3]);
            }
        }
    }
}

// ---------------------------------------------------------------------------
// Launch
// ---------------------------------------------------------------------------
extern "C" void kernel_launch(void* const* d_in, const int* in_sizes, int n_in,
                              void* d_out, int out_size) {
    const float* query = (const float*)d_in[0];
    const float* key   = (const float*)d_in[1];
    const float* prox  = (const float*)d_in[2];
    const int*   cls   = (const int*)d_in[3];

    const int Q = in_sizes[0] / D_DIM;   // 4096
    const int S = in_sizes[1] / D_DIM;   // 8192
    const int C = in_sizes[2] / D_DIM;   // 1000
    float* out = (float*)d_out;

    __nv_bfloat16 *qnh, *knh, *attn;
    float *a2, *gram;
    cudaGetSymbolAddress((void**)&qnh,  g_qnh);
    cudaGetSymbolAddress((void**)&knh,  g_knh);
    cudaGetSymbolAddress((void**)&attn, g_attn);
    cudaGetSymbolAddress((void**)&a2,   g_a2);
    cudaGetSymbolAddress((void**)&gram, g_gram);

    cudaFuncSetAttribute(g1_bf16_kernel, cudaFuncAttributeMaxDynamicSharedMemorySize, G1_SMEM);

    cls_convert_kernel<<<(S + 255) / 256, 256>>>(cls, S);
    l2norm_bf16_kernel<<<Q, 256>>>(query, qnh);
    l2norm_bf16_kernel<<<S, 256>>>(key, knh);

    // G1: attn = exp(qn @ kn^T - 1), bf16 -> bf16
    {
        dim3 grid(S / 128, Q / 128);
        g1_bf16_kernel<<<grid, 256, G1_SMEM>>>(qnh, knh, attn, Q, S, D_DIM);
    }

    // Gram: G[c',c] = P[c'] . P[c]  (tf32)
    {
        dim3 grid((C + 127) / 128, (C + 127) / 128);
        gemm_tf32_nt<true, true><<<grid, 256>>>(prox, prox, gram, C, C, D_DIM, D_DIM, D_DIM, CPAD);
    }

    // A2
    a2_kernel<<<Q, 256>>>(attn, a2, S);

    // logits = A2 @ Gram^T (tf32)
    {
        dim3 grid((C + 127) / 128, Q / 128);
        gemm_tf32_nt<false, false><<<grid, 256>>>(a2, gram, out, Q, C, CPAD, CPAD, CPAD, C);
    }
}

// round 6
// speedup vs baseline: 6.6757x; 1.2027x over previous
#include <cuda_runtime.h>
#include <cuda_bf16.h>
#include <cuda_fp16.h>
#include <math.h>
#include <stdint.h>

#define D_DIM 512
#define MAXQ 4096
#define MAXS 8192
#define CPAD 1024
#define NCLS 1000

// ---------------------------------------------------------------------------
// Static scratch
// ---------------------------------------------------------------------------
__device__ __nv_bfloat16 g_qnh[(size_t)MAXQ * D_DIM];   // normalized queries, bf16
__device__ __nv_bfloat16 g_knh[(size_t)MAXS * D_DIM];   // normalized keys (class-sorted rows)
__device__ __nv_bfloat16 g_attn[(size_t)MAXQ * MAXS];   // exp kernel, bf16 (cols class-sorted)
__device__ __half g_a2h[(size_t)MAXQ * CPAD];           // class sums, fp16 (pad cols = 0)
__device__ __half g_gram16[(size_t)NCLS * CPAD];        // P @ P^T fp16 (pad cols stay 0)
__device__ __half g_p16[(size_t)NCLS * D_DIM];          // proxies fp16
__device__ int g_perm[MAXS];                            // original idx -> sorted pos
__device__ int g_start[CPAD + 1];                       // class segment starts

// ---------------------------------------------------------------------------
// Helpers (portable sm_80+ PTX; toolchain targets plain sm_100)
// ---------------------------------------------------------------------------
__device__ __forceinline__ uint32_t smem_u32(const void* p) {
    uint32_t a;
    asm("{ .reg .u64 t; cvta.to.shared.u64 t, %1; cvt.u32.u64 %0, t; }" : "=r"(a) : "l"(p));
    return a;
}
__device__ __forceinline__ void cp16(uint32_t dst_smem, const void* src) {
    asm volatile("cp.async.cg.shared.global [%0], [%1], 16;\n" :: "r"(dst_smem), "l"(src));
}
__device__ __forceinline__ void cp_commit() { asm volatile("cp.async.commit_group;\n" ::: "memory"); }
__device__ __forceinline__ void cp_wait0() { asm volatile("cp.async.wait_group 0;\n" ::: "memory"); }
__device__ __forceinline__ void cp_wait1() { asm volatile("cp.async.wait_group 1;\n" ::: "memory"); }
__device__ __forceinline__ void cp_wait2() { asm volatile("cp.async.wait_group 2;\n" ::: "memory"); }

__device__ __forceinline__ void ldm_x4(uint32_t* r, uint32_t addr) {
    asm volatile("ldmatrix.sync.aligned.m8n8.x4.shared.b16 {%0,%1,%2,%3}, [%4];"
                 : "=r"(r[0]), "=r"(r[1]), "=r"(r[2]), "=r"(r[3]) : "r"(addr));
}
__device__ __forceinline__ void mma_bf16(float* c, const uint32_t* a, const uint32_t* b) {
    asm volatile(
        "mma.sync.aligned.m16n8k16.row.col.f32.bf16.bf16.f32 "
        "{%0,%1,%2,%3}, {%4,%5,%6,%7}, {%8,%9}, {%0,%1,%2,%3};\n"
        : "+f"(c[0]), "+f"(c[1]), "+f"(c[2]), "+f"(c[3])
        : "r"(a[0]), "r"(a[1]), "r"(a[2]), "r"(a[3]), "r"(b[0]), "r"(b[1]));
}
__device__ __forceinline__ void mma_f16(float* c, const uint32_t* a, const uint32_t* b) {
    asm volatile(
        "mma.sync.aligned.m16n8k16.row.col.f32.f16.f16.f32 "
        "{%0,%1,%2,%3}, {%4,%5,%6,%7}, {%8,%9}, {%0,%1,%2,%3};\n"
        : "+f"(c[0]), "+f"(c[1]), "+f"(c[2]), "+f"(c[3])
        : "r"(a[0]), "r"(a[1]), "r"(a[2]), "r"(a[3]), "r"(b[0]), "r"(b[1]));
}

// ---------------------------------------------------------------------------
// Deterministic stable counting sort of supports by class.
// Single block, 1024 threads. Chunked two-pass: per-chunk serial counting
// (exclusive per chunk -> no atomics -> deterministic stable ranks).
// ---------------------------------------------------------------------------
#define SORT_NCH 16
#define SORT_SMEM ((MAXS + SORT_NCH * CPAD + CPAD + CPAD) * 4)

__global__ void cls_sort_kernel(const int* __restrict__ raw, int S) {
    extern __shared__ int sm[];
    int* cls_sm = sm;                       // [S]
    int* counts = sm + MAXS;                // [SORT_NCH][CPAD]
    int* tot    = counts + SORT_NCH * CPAD; // [CPAD]
    int* stt    = tot + CPAD;               // [CPAD]
    const int tid = threadIdx.x;

    __shared__ int is64s;
    if (tid == 0) {
        int is64 = 1;
        int nw = S < 64 ? S : 64;
        for (int i = 1; i < nw; i += 2)
            if (raw[i] != 0) { is64 = 0; break; }
        is64s = is64;
    }
    __syncthreads();

    for (int s = tid; s < S; s += 1024)
        cls_sm[s] = is64s ? (int)((const long long*)raw)[s] : raw[s];
    for (int i = tid; i < SORT_NCH * CPAD; i += 1024) counts[i] = 0;
    __syncthreads();

    const int csz = (S + SORT_NCH - 1) / SORT_NCH;
    if (tid < SORT_NCH) {
        int* cnt = counts + tid * CPAD;
        int lo = tid * csz, hi = min(S, lo + csz);
        for (int s = lo; s < hi; s++) cnt[cls_sm[s]]++;
    }
    __syncthreads();

    {
        int t = 0;
        #pragma unroll
        for (int ch = 0; ch < SORT_NCH; ch++) t += counts[ch * CPAD + tid];
        tot[tid] = t;
    }
    __syncthreads();

    if (tid == 0) {
        int run = 0;
        for (int c = 0; c < CPAD; c++) { stt[c] = run; run += tot[c]; }
    }
    __syncthreads();

    {
        int run = stt[tid];
        #pragma unroll
        for (int ch = 0; ch < SORT_NCH; ch++) {
            int t = counts[ch * CPAD + tid];
            counts[ch * CPAD + tid] = run;
            run += t;
        }
    }
    __syncthreads();

    if (tid < SORT_NCH) {
        int* cnt = counts + tid * CPAD;
        int lo = tid * csz, hi = min(S, lo + csz);
        for (int s = lo; s < hi; s++) {
            int c = cls_sm[s];
            g_perm[s] = cnt[c]++;
        }
    }
    g_start[tid] = stt[tid];
    if (tid == 0) g_start[CPAD] = S;
}

// ---------------------------------------------------------------------------
// L2 normalize rows -> bf16 (RN); PERMUTE: write to row perm[blockIdx.x]
// ---------------------------------------------------------------------------
template <bool PERM>
__global__ void l2norm_bf16_kernel(const float* __restrict__ in, __nv_bfloat16* __restrict__ out) {
    int row = blockIdx.x;
    const float* x = in + (size_t)row * D_DIM;
    int orow = PERM ? g_perm[row] : row;
    __nv_bfloat16* y = out + (size_t)orow * D_DIM;
    int tid = threadIdx.x;

    float v0 = x[tid];
    float v1 = x[tid + 256];
    float s = v0 * v0 + v1 * v1;
    #pragma unroll
    for (int o = 16; o > 0; o >>= 1) s += __shfl_xor_sync(0xffffffffu, s, o);

    __shared__ float ws[8];
    if ((tid & 31) == 0) ws[tid >> 5] = s;
    __syncthreads();
    if (tid < 8) {
        float t = ws[tid];
        #pragma unroll
        for (int o = 4; o > 0; o >>= 1) t += __shfl_xor_sync(0xffu, t, o);
        if (tid == 0) ws[0] = t;
    }
    __syncthreads();

    float inv = 1.0f / fmaxf(sqrtf(ws[0]), 1e-12f);
    y[tid] = __float2bfloat16_rn(v0 * inv);
    y[tid + 256] = __float2bfloat16_rn(v1 * inv);
}

// ---------------------------------------------------------------------------
// P -> fp16
// ---------------------------------------------------------------------------
__global__ void p16_kernel(const float* __restrict__ P, int n) {
    int i = blockIdx.x * blockDim.x + threadIdx.x;
    if (i < n) g_p16[i] = __float2half_rn(P[i]);
}

// ---------------------------------------------------------------------------
// G1: attn[Q,S] = exp(A @ B^T - 1) in bf16 (unchanged from round 5).
// ---------------------------------------------------------------------------
#define G1_PITCH 40
#define G1_TILE_ELEMS (128 * G1_PITCH)
#define G1_STAGE_BYTES (G1_TILE_ELEMS * 2)
#define G1_SMEM (6 * G1_STAGE_BYTES)

__global__ __launch_bounds__(256, 2)
void g1_bf16_kernel(const __nv_bfloat16* __restrict__ A, const __nv_bfloat16* __restrict__ B,
                    __nv_bfloat16* __restrict__ C, int M, int N, int K) {
    extern __shared__ __nv_bfloat16 smem[];
    const uint32_t sb = smem_u32(smem);

    const int tid = threadIdx.x;
    const int lane = tid & 31;
    const int wid = tid >> 5;
    const int wm = (wid & 3) * 32;
    const int wn = (wid >> 2) * 64;
    const int g = lane >> 2;
    const int t = lane & 3;
    const int lr = lane & 7;
    const int lb3 = (lane >> 3) & 1;
    const int lb4 = (lane >> 4) & 1;
    const int m0 = blockIdx.y * 128;
    const int n0 = blockIdx.x * 128;

    float acc[2][8][4];
    #pragma unroll
    for (int i = 0; i < 2; i++)
        #pragma unroll
        for (int j = 0; j < 8; j++)
            #pragma unroll
            for (int r = 0; r < 4; r++) acc[i][j][r] = 0.0f;

    const int srow = tid >> 2;
    const int scol = (tid & 3) * 8;
    auto stage = [&](int s, int k0) {
        uint32_t abase = sb + s * (uint32_t)G1_STAGE_BYTES;
        uint32_t bbase = sb + (uint32_t)(3 * G1_STAGE_BYTES) + s * (uint32_t)G1_STAGE_BYTES;
        #pragma unroll
        for (int h = 0; h < 2; h++) {
            int row = srow + h * 64;
            cp16(abase + (row * G1_PITCH + scol) * 2, A + (size_t)(m0 + row) * K + k0 + scol);
            cp16(bbase + (row * G1_PITCH + scol) * 2, B + (size_t)(n0 + row) * K + k0 + scol);
        }
        cp_commit();
    };

    const int KT = K / 32;
    stage(0, 0);
    stage(1, 32);

    for (int it = 0; it < KT; it++) {
        if (it + 2 < KT) stage((it + 2) % 3, (it + 2) * 32);
        const int rem = KT - 1 - it;
        if (rem >= 2) cp_wait2();
        else if (rem == 1) cp_wait1();
        else cp_wait0();
        __syncthreads();

        const int buf = it % 3;
        const uint32_t abase = sb + buf * (uint32_t)G1_STAGE_BYTES;
        const uint32_t bbase = sb + (uint32_t)(3 * G1_STAGE_BYTES) + buf * (uint32_t)G1_STAGE_BYTES;

        #pragma unroll
        for (int kk = 0; kk < 2; kk++) {
            uint32_t af[2][4];
            #pragma unroll
            for (int i = 0; i < 2; i++) {
                int row = wm + i * 16 + lb3 * 8 + lr;
                int col = kk * 16 + lb4 * 8;
                ldm_x4(af[i], abase + (row * G1_PITCH + col) * 2);
            }
            uint32_t bf[4][4];
            #pragma unroll
            for (int jp = 0; jp < 4; jp++) {
                int row = wn + jp * 16 + lb4 * 8 + lr;
                int col = kk * 16 + lb3 * 8;
                ldm_x4(bf[jp], bbase + (row * G1_PITCH + col) * 2);
            }
            #pragma unroll
            for (int i = 0; i < 2; i++)
                #pragma unroll
                for (int jp = 0; jp < 4; jp++) {
                    mma_bf16(acc[i][2 * jp],     af[i], &bf[jp][0]);
                    mma_bf16(acc[i][2 * jp + 1], af[i], &bf[jp][2]);
                }
        }
        __syncthreads();
    }

    #pragma unroll
    for (int i = 0; i < 2; i++) {
        int r0 = m0 + wm + i * 16 + g;
        #pragma unroll
        for (int j = 0; j < 8; j++) {
            int col = n0 + wn + j * 8 + 2 * t;
            __nv_bfloat162 p0 = __floats2bfloat162_rn(
                __expf(acc[i][j][0] - 1.0f), __expf(acc[i][j][1] - 1.0f));
            __nv_bfloat162 p1 = __floats2bfloat162_rn(
                __expf(acc[i][j][2] - 1.0f), __expf(acc[i][j][3] - 1.0f));
            *(__nv_bfloat162*)(C + (size_t)r0 * N + col) = p0;
            *(__nv_bfloat162*)(C + (size_t)(r0 + 8) * N + col) = p1;
        }
    }
}

// ---------------------------------------------------------------------------
// A2: segmented class sums (attn cols are class-sorted). Deterministic fp32
// serial sums per segment; no atomics. Output fp16 with zero pad.
// ---------------------------------------------------------------------------
__global__ void a2_seg_kernel(const __nv_bfloat16* __restrict__ attn, int S) {
    __shared__ uint4 rowbuf[MAXS / 8];   // 16 KB
    const int q = blockIdx.x;
    const int tid = threadIdx.x;

    const uint4* src = (const uint4*)(attn + (size_t)q * S);
    for (int i = tid; i < S / 8; i += 256) rowbuf[i] = src[i];
    __syncthreads();

    const __nv_bfloat16* row = (const __nv_bfloat16*)rowbuf;
    #pragma unroll
    for (int u = 0; u < 4; u++) {
        int c = tid * 4 + u;
        int lo = g_start[c];
        int hi = g_start[c + 1];
        float s = 0.0f;
        for (int k = lo; k < hi; k++) s += __bfloat162float(row[k]);
        g_a2h[(size_t)q * CPAD + c] = __float2half_rn(s);
    }
}

// ---------------------------------------------------------------------------
// fp16 NT GEMM: C[M,N] = A[M,K] @ B[N,K]^T. Same architecture as G1
// (ldmatrix, 128x128 tile, BK=32, 3-stage). Clamped loads, guarded stores.
// K mult of 32; N even. OUT_HALF: store __half2 else float2.
// ---------------------------------------------------------------------------
template <bool OUT_HALF>
__global__ __launch_bounds__(256, 2)
void gemm_h16_kernel(const __half* __restrict__ A, const __half* __restrict__ B,
                     void* __restrict__ Cout, int M, int N, int K,
                     int lda, int ldb, int ldc) {
    extern __shared__ __nv_bfloat16 smem[];
    const uint32_t sb = smem_u32(smem);

    const int tid = threadIdx.x;
    const int lane = tid & 31;
    const int wid = tid >> 5;
    const int wm = (wid & 3) * 32;
    const int wn = (wid >> 2) * 64;
    const int g = lane >> 2;
    const int t = lane & 3;
    const int lr = lane & 7;
    const int lb3 = (lane >> 3) & 1;
    const int lb4 = (lane >> 4) & 1;
    const int m0 = blockIdx.y * 128;
    const int n0 = blockIdx.x * 128;

    float acc[2][8][4];
    #pragma unroll
    for (int i = 0; i < 2; i++)
        #pragma unroll
        for (int j = 0; j < 8; j++)
            #pragma unroll
            for (int r = 0; r < 4; r++) acc[i][j][r] = 0.0f;

    const int srow = tid >> 2;
    const int scol = (tid & 3) * 8;
    auto stage = [&](int s, int k0) {
        uint32_t abase = sb + s * (uint32_t)G1_STAGE_BYTES;
        uint32_t bbase = sb + (uint32_t)(3 * G1_STAGE_BYTES) + s * (uint32_t)G1_STAGE_BYTES;
        #pragma unroll
        for (int h = 0; h < 2; h++) {
            int row = srow + h * 64;
            int ar = m0 + row; if (ar > M - 1) ar = M - 1;
            int br = n0 + row; if (br > N - 1) br = N - 1;
            cp16(abase + (row * G1_PITCH + scol) * 2, A + (size_t)ar * lda + k0 + scol);
            cp16(bbase + (row * G1_PITCH + scol) * 2, B + (size_t)br * ldb + k0 + scol);
        }
        cp_commit();
    };

    const int KT = K / 32;
    stage(0, 0);
    stage(1, 32);

    for (int it = 0; it < KT; it++) {
        if (it + 2 < KT) stage((it + 2) % 3, (it + 2) * 32);
        const int rem = KT - 1 - it;
        if (rem >= 2) cp_wait2();
        else if (rem == 1) cp_wait1();
        else cp_wait0();
        __syncthreads();

        const int buf = it % 3;
        const uint32_t abase = sb + buf * (uint32_t)G1_STAGE_BYTES;
        const uint32_t bbase = sb + (uint32_t)(3 * G1_STAGE_BYTES) + buf * (uint32_t)G1_STAGE_BYTES;

        #pragma unroll
        for (int kk = 0; kk < 2; kk++) {
            uint32_t af[2][4];
            #pragma unroll
            for (int i = 0; i < 2; i++) {
                int row = wm + i * 16 + lb3 * 8 + lr;
                int col = kk * 16 + lb4 * 8;
                ldm_x4(af[i], abase + (row * G1_PITCH + col) * 2);
            }
            uint32_t bf[4][4];
            #pragma unroll
            for (int jp = 0; jp < 4; jp++) {
                int row = wn + jp * 16 + lb4 * 8 + lr;
                int col = kk * 16 + lb3 * 8;
                ldm_x4(bf[jp], bbase + (row * G1_PITCH + col) * 2);
            }
            #pragma unroll
            for (int i = 0; i < 2; i++)
                #pragma unroll
                for (int jp = 0; jp < 4; jp++) {
                    mma_f16(acc[i][2 * jp],     af[i], &bf[jp][0]);
                    mma_f16(acc[i][2 * jp + 1], af[i], &bf[jp][2]);
                }
        }
        __syncthreads();
    }

    #pragma unroll
    for (int i = 0; i < 2; i++) {
        int r0 = m0 + wm + i * 16 + g;
        #pragma unroll
        for (int j = 0; j < 8; j++) {
            int col = n0 + wn + j * 8 + 2 * t;
            if (col < N) {   // N even; pair never straddles
                if (OUT_HALF) {
                    __half* C = (__half*)Cout;
                    __half2 p0 = __floats2half2_rn(acc[i][j][0], acc[i][j][1]);
                    __half2 p1 = __floats2half2_rn(acc[i][j][2], acc[i][j][3]);
                    if (r0 < M)     *(__half2*)(C + (size_t)r0 * ldc + col) = p0;
                    if (r0 + 8 < M) *(__half2*)(C + (size_t)(r0 + 8) * ldc + col) = p1;
                } else {
                    float* C = (float*)Cout;
                    if (r0 < M)
                        *(float2*)(C + (size_t)r0 * ldc + col) = make_float2(acc[i][j][0], acc[i][j][1]);
                    if (r0 + 8 < M)
                        *(float2*)(C + (size_t)(r0 + 8) * ldc + col) = make_float2(acc[i][j][2], acc[i][j][3]);
                }
            }
        }
    }
}

// ---------------------------------------------------------------------------
// Launch
// ---------------------------------------------------------------------------
extern "C" void kernel_launch(void* const* d_in, const int* in_sizes, int n_in,
                              void* d_out, int out_size) {
    const float* query = (const float*)d_in[0];
    const float* key   = (const float*)d_in[1];
    const float* prox  = (const float*)d_in[2];
    const int*   cls   = (const int*)d_in[3];

    const int Q = in_sizes[0] / D_DIM;   // 4096
    const int S = in_sizes[1] / D_DIM;   // 8192
    const int C = in_sizes[2] / D_DIM;   // 1000
    float* out = (float*)d_out;

    __nv_bfloat16 *qnh, *knh, *attn;
    __half *a2h, *gram16, *p16;
    cudaGetSymbolAddress((void**)&qnh,    g_qnh);
    cudaGetSymbolAddress((void**)&knh,    g_knh);
    cudaGetSymbolAddress((void**)&attn,   g_attn);
    cudaGetSymbolAddress((void**)&a2h,    g_a2h);
    cudaGetSymbolAddress((void**)&gram16, g_gram16);
    cudaGetSymbolAddress((void**)&p16,    g_p16);

    cudaFuncSetAttribute(g1_bf16_kernel, cudaFuncAttributeMaxDynamicSharedMemorySize, G1_SMEM);
    cudaFuncSetAttribute(gemm_h16_kernel<true>, cudaFuncAttributeMaxDynamicSharedMemorySize, G1_SMEM);
    cudaFuncSetAttribute(gemm_h16_kernel<false>, cudaFuncAttributeMaxDynamicSharedMemorySize, G1_SMEM);
    cudaFuncSetAttribute(cls_sort_kernel, cudaFuncAttributeMaxDynamicSharedMemorySize, SORT_SMEM);

    // 1. deterministic class sort (perm + segment starts)
    cls_sort_kernel<<<1, 1024, SORT_SMEM>>>(cls, S);

    // 2. normalize (keys written in class-sorted order)
    l2norm_bf16_kernel<false><<<Q, 256>>>(query, qnh);
    l2norm_bf16_kernel<true><<<S, 256>>>(key, knh);

    // 3. proxies -> fp16
    p16_kernel<<<(C * D_DIM + 255) / 256, 256>>>(prox, C * D_DIM);

    // 4. G1: attn = exp(qn @ kn^T - 1), bf16 -> bf16 (cols class-sorted)
    {
        dim3 grid(S / 128, Q / 128);
        g1_bf16_kernel<<<grid, 256, G1_SMEM>>>(qnh, knh, attn, Q, S, D_DIM);
    }

    // 5. Gram = P @ P^T, fp16 (pad cols of g_gram16 never written, stay 0)
    {
        dim3 grid((C + 127) / 128, (C + 127) / 128);
        gemm_h16_kernel<true><<<grid, 256, G1_SMEM>>>(
            p16, p16, gram16, C, C, D_DIM, D_DIM, D_DIM, CPAD);
    }

    // 6. A2: segmented class sums -> fp16
    a2_seg_kernel<<<Q, 256>>>(attn, S);

    // 7. logits = A2 @ Gram^T, fp16 -> fp32
    {
        dim3 grid((C + 127) / 128, Q / 128);
        gemm_h16_kernel<false><<<grid, 256, G1_SMEM>>>(
            a2h, gram16, out, Q, C, CPAD, CPAD, CPAD, C);
    }
}